// round 17
// baseline (speedup 1.0000x reference)
#include <cuda_runtime.h>
#include <cuda_fp16.h>

#define BB 256
#define DD 564
#define SS 40
#define PP 20
#define NBL 6
#define NCOL 2256      /* 4*DD */
#define ROWS 10240     /* BB*SS */
#define OUTIN 1128
#define KP 288         /* k-pairs (576/2) */
#define NKCW 18        /* wgemm k-chunks of 16 kp */
#define CBLK 36
#define BBLK 4

// ---------------- scratch (static device globals; no allocation) ----------------
__device__ float g_x[ROWS * DD];           // activations (b,s,d)
__device__ float g_pre[SS * BB * NCOL];    // (s,b, e*4+g)  gate-interleaved
__device__ float g_mean[DD];
__device__ float g_rstd[DD];
__device__ unsigned g_bcnt[BBLK * 32];
__device__ unsigned g_bgen[BBLK * 32];
__device__ unsigned g_hh16[ROWS * KP];     // layernorm out, fp16x2 single plane
__device__ uint2 g_W16[4 * KP * DD];       // W  [g][kp][e]  {hi2, lo2}  (2-term)
__device__ unsigned g_Rh16[KP * NCOL];     // R  [kp][e*4+g] fp16x2 single plane
__device__ unsigned g_hh[2][BB * KP];      // scan hidden state fp16x2, dbl-buffered

// ---------------- fp16 split helpers ----------------
__device__ __forceinline__ uint2 pack_split(float x0, float x1) {
    __half h0 = __float2half_rn(x0), h1 = __float2half_rn(x1);
    __half l0 = __float2half_rn(x0 - __half2float(h0));
    __half l1 = __float2half_rn(x1 - __half2float(h1));
    uint2 r;
    r.x = (unsigned)__half_as_ushort(h0) | ((unsigned)__half_as_ushort(h1) << 16);
    r.y = (unsigned)__half_as_ushort(l0) | ((unsigned)__half_as_ushort(l1) << 16);
    return r;
}
__device__ __forceinline__ unsigned pack_hi2(float x0, float x1) {
    return (unsigned)__half_as_ushort(__float2half_rn(x0)) |
           ((unsigned)__half_as_ushort(__float2half_rn(x1)) << 16);
}
__device__ __forceinline__ void mma16(float* d, const unsigned* a, const unsigned* b) {
    asm volatile(
        "mma.sync.aligned.m16n8k16.row.col.f32.f16.f16.f32 "
        "{%0,%1,%2,%3}, {%4,%5,%6,%7}, {%8,%9}, {%0,%1,%2,%3};"
        : "+f"(d[0]), "+f"(d[1]), "+f"(d[2]), "+f"(d[3])
        : "r"(a[0]), "r"(a[1]), "r"(a[2]), "r"(a[3]), "r"(b[0]), "r"(b[1]));
}
__device__ __forceinline__ void cpasync16(unsigned dst, const void* src) {
    asm volatile("cp.async.cg.shared.global [%0], [%1], 16;" :: "r"(dst), "l"(src));
}
__device__ __forceinline__ void cpasync_commit() {
    asm volatile("cp.async.commit_group;");
}
template <int N>
__device__ __forceinline__ void cpasync_wait() {
    asm volatile("cp.async.wait_group %0;" :: "n"(N));
}

// ---------------- input reshape ----------------
__global__ void k_reshape(const float* __restrict__ inp) {
    int idx = blockIdx.x * blockDim.x + threadIdx.x;
    if (idx >= ROWS * DD) return;
    int d = idx % DD;
    int r = idx / DD;
    int s = r % SS;
    int b = r / SS;
    g_x[idx] = inp[(size_t)b * (DD * SS) + d * SS + s];
}

// ---------------- weight conversion (per layer) ----------------
__global__ void k_convW(const float* __restrict__ W) {
    int idx = blockIdx.x * blockDim.x + threadIdx.x;
    if (idx >= 4 * KP * DD) return;
    int g = idx / (KP * DD);
    int rem = idx - g * KP * DD;
    int kp = rem / DD;
    int e  = rem - kp * DD;
    int d0 = kp * 2, d1 = d0 + 1;
    float x0 = (d0 < DD) ? W[(size_t)g * DD * DD + (size_t)d0 * DD + e] : 0.f;
    float x1 = (d1 < DD) ? W[(size_t)g * DD * DD + (size_t)d1 * DD + e] : 0.f;
    g_W16[idx] = pack_split(x0, x1);
}
__global__ void k_convR(const float* __restrict__ R) {
    int idx = blockIdx.x * blockDim.x + threadIdx.x;
    if (idx >= KP * NCOL) return;
    int kp  = idx / NCOL;
    int col = idx - kp * NCOL;
    int e = col >> 2, g = col & 3;
    int d0 = kp * 2, d1 = d0 + 1;
    float x0 = (d0 < DD) ? R[(size_t)g * DD * DD + (size_t)d0 * DD + e] : 0.f;
    float x1 = (d1 < DD) ? R[(size_t)g * DD * DD + (size_t)d1 * DD + e] : 0.f;
    g_Rh16[idx] = pack_hi2(x0, x1);
}

// ---------------- layernorm: emits fp16 single-plane h ----------------
__global__ void k_layernorm(const float* __restrict__ lng, const float* __restrict__ lnb) {
    int row = blockIdx.x;
    const float* xr = g_x + (size_t)row * DD;
    __shared__ float red[128];
    __shared__ float s_mu, s_rs;
    float s1 = 0.f, s2 = 0.f;
    for (int d = threadIdx.x; d < DD; d += 128) { float v = xr[d]; s1 += v; s2 += v * v; }
    red[threadIdx.x] = s1; __syncthreads();
    for (int o = 64; o > 0; o >>= 1) { if (threadIdx.x < o) red[threadIdx.x] += red[threadIdx.x + o]; __syncthreads(); }
    if (threadIdx.x == 0) s_mu = red[0] / DD;
    __syncthreads();
    red[threadIdx.x] = s2; __syncthreads();
    for (int o = 64; o > 0; o >>= 1) { if (threadIdx.x < o) red[threadIdx.x] += red[threadIdx.x + o]; __syncthreads(); }
    if (threadIdx.x == 0) {
        float var = red[0] / DD - s_mu * s_mu;
        s_rs = rsqrtf(var + 1e-5f);
    }
    __syncthreads();
    float mu = s_mu, rs = s_rs;
    for (int kp = threadIdx.x; kp < KP; kp += 128) {
        int d0 = kp * 2, d1 = d0 + 1;
        float x0 = (d0 < DD) ? (xr[d0] - mu) * rs * lng[d0] + lnb[d0] : 0.f;
        float x1 = (d1 < DD) ? (xr[d1] - mu) * rs * lng[d1] + lnb[d1] : 0.f;
        g_hh16[(size_t)row * KP + kp] = pack_hi2(x0, x1);
    }
}

// ---------------- W GEMM: 2-term split (A fp16, W hi+lo) — unchanged from R16 ----------------
__global__ void __launch_bounds__(128) k_wgemm(const float* __restrict__ bias) {
    __shared__ unsigned sA[64 * 20];   // [row][kp0..15], stride 20
    __shared__ uint2 sB[16 * 68];      // [kp][e0..63],   stride 68
    int g  = blockIdx.z;
    int n0 = blockIdx.x * 64;
    int m0 = blockIdx.y * 64;
    int t = threadIdx.x, lane = t & 31, wid = t >> 5;
    int wm = wid >> 1, wn = wid & 1;

    float acc[2][4][4];
#pragma unroll
    for (int i = 0; i < 2; i++)
#pragma unroll
        for (int j = 0; j < 4; j++)
#pragma unroll
            for (int k = 0; k < 4; k++) acc[i][j][k] = 0.f;

    const uint2* Wbase = g_W16 + (size_t)g * KP * DD;

    for (int kc = 0; kc < NKCW; kc++) {
        {   // A: 64 rows x 16 kp fp16x2; 8 uints per thread
            int row = t >> 1, kb = (t & 1) * 8;
            const unsigned* src = g_hh16 + (size_t)(m0 + row) * KP + kc * 16 + kb;
            unsigned* dst = sA + row * 20 + kb;
            *(uint4*)(dst)     = *(const uint4*)(src);
            *(uint4*)(dst + 4) = *(const uint4*)(src + 4);
        }
        {
#pragma unroll
            for (int it = 0; it < 8; it++) {
                int i = t + it * 128;
                int kpr = i >> 6, c = i & 63;
                int ge = n0 + c;
                uint2 v = make_uint2(0u, 0u);
                if (ge < DD) v = Wbase[(size_t)(kc * 16 + kpr) * DD + ge];
                sB[kpr * 68 + c] = v;
            }
        }
        __syncthreads();
#pragma unroll
        for (int ts = 0; ts < 2; ts++) {
            int kpf = ts * 8 + (lane & 3);
            unsigned a[2][4];
#pragma unroll
            for (int mi = 0; mi < 2; mi++) {
                int row = wm * 32 + mi * 16 + (lane >> 2);
                const unsigned* Ap = sA + row * 20;
                a[mi][0] = Ap[kpf];       a[mi][1] = Ap[160 + kpf];
                a[mi][2] = Ap[kpf + 4];   a[mi][3] = Ap[160 + kpf + 4];
            }
#pragma unroll
            for (int ni = 0; ni < 4; ni++) {
                int cb = wn * 32 + ni * 8 + (lane >> 2);
                uint2 b0 = sB[kpf * 68 + cb];
                uint2 b1 = sB[(kpf + 4) * 68 + cb];
                unsigned bh[2] = {b0.x, b1.x};
                unsigned bl[2] = {b0.y, b1.y};
#pragma unroll
                for (int mi = 0; mi < 2; mi++) {
                    mma16(acc[mi][ni], a[mi], bh);
                    mma16(acc[mi][ni], a[mi], bl);
                }
            }
        }
        __syncthreads();
    }
    const float* bp = bias + g * DD;
#pragma unroll
    for (int mi = 0; mi < 2; mi++) {
        int row0 = m0 + wm * 32 + mi * 16 + (lane >> 2);
        int row1 = row0 + 8;
        int b0r = row0 / SS, s0r = row0 - b0r * SS;
        int b1r = row1 / SS, s1r = row1 - b1r * SS;
        float* o0 = g_pre + (size_t)(s0r * BB + b0r) * NCOL + g;
        float* o1 = g_pre + (size_t)(s1r * BB + b1r) * NCOL + g;
#pragma unroll
        for (int ni = 0; ni < 4; ni++) {
            int e = n0 + wn * 32 + ni * 8 + (lane & 3) * 2;
            if (e < DD) {
                float bv0 = bp[e], bv1 = bp[e + 1];
                o0[(e) * 4]     = acc[mi][ni][0] + bv0;
                o0[(e + 1) * 4] = acc[mi][ni][1] + bv1;
                o1[(e) * 4]     = acc[mi][ni][2] + bv0;
                o1[(e + 1) * 4] = acc[mi][ni][3] + bv1;
            }
        }
    }
}

// ---------------- persistent scan: 512 thr, 1-term fp16, 3 chunks of 96 kp ----------------
#define SB_SZ (KP * 68 * 4)            /* 78336: R fp16 plane persistent */
#define SA_STR 100                     /* uint stride (==4 mod 8) */
#define SA_BUF (64 * SA_STR)           /* 6400 uints per buffer */
#define SA_SZ (2 * SA_BUF * 4)         /* 51200 */
#define SCAN_SMEM (SB_SZ + SA_SZ)      /* 129536 */
#define NCH 3
#define CHKP 96

__device__ __forceinline__ void group_barrier(int grp, unsigned target) {
    __threadfence();
    __syncthreads();
    if (threadIdx.x == 0) {
        unsigned arr = atomicAdd(&g_bcnt[grp * 32], 1u);
        if (arr == CBLK - 1u) {
            *((volatile unsigned*)&g_bcnt[grp * 32]) = 0u;
            __threadfence();
            atomicExch(&g_bgen[grp * 32], target);
        } else {
            while (*((volatile unsigned*)&g_bgen[grp * 32]) < target) __nanosleep(32);
            __threadfence();
        }
    }
    __syncthreads();
}

__global__ void __launch_bounds__(512, 1) k_scan() {
    extern __shared__ char smraw[];
    unsigned* sB = (unsigned*)smraw;                // [kp][c], stride 68
    unsigned* sA = (unsigned*)(smraw + SB_SZ);      // 2 x [row][kp0..95], stride 100

    int t = threadIdx.x, lane = t & 31;
    int wid = t >> 5, wm = wid >> 2, wn = wid & 3;  // 4 x 4 warp grid
    int cb0 = blockIdx.x * 64;
    int b0  = blockIdx.y * 64;
    int grp = blockIdx.y;

    // fill persistent R tile (fp16 plane)
    for (int i = t; i < KP * 64; i += 512) {
        int kp = i >> 6, c = i & 63;
        int gc = cb0 + c;
        unsigned v = 0u;
        if (gc < NCOL) v = g_Rh16[(size_t)kp * NCOL + gc];
        sB[kp * 68 + c] = v;
    }

    // zero h0 plane (redundant across col-blocks; benign)
    for (int i = t; i < 64 * KP; i += 512) g_hh[0][(size_t)b0 * KP + i] = 0u;

    // per-thread sLSTM state (live on even lanes): [ni][rr]
    float scst[2][2], snst[2][2], smst[2][2];
#pragma unroll
    for (int a = 0; a < 2; a++)
#pragma unroll
        for (int b = 0; b < 2; b++) { scst[a][b] = 0.f; snst[a][b] = 0.f; smst[a][b] = 0.f; }

    unsigned target = *((volatile unsigned*)&g_bgen[grp * 32]);
    ++target; group_barrier(grp, target);

    // staging: 64 rows x 96 uints per chunk; 12 uints (3x16B) per thread
    const int arow = t >> 3, abase = (t & 7) * 12;
    unsigned sAu = (unsigned)__cvta_generic_to_shared(sA);

    for (int s = 0; s < SS; s++) {
        const unsigned* hsrc = g_hh[s & 1] + (size_t)(b0 + arow) * KP + abase;
        unsigned* hnxt = g_hh[(s & 1) ^ 1];

        float acc[2][4];
#pragma unroll
        for (int i = 0; i < 2; i++)
#pragma unroll
            for (int k = 0; k < 4; k++) acc[i][k] = 0.f;

        // stage chunk 0 into buf 0
        {
            unsigned dst = sAu + (arow * SA_STR + abase) * 4;
#pragma unroll
            for (int j = 0; j < 3; j++) cpasync16(dst + j * 16, hsrc + j * 4);
            cpasync_commit();
            cpasync_wait<0>();
        }
        __syncthreads();

        for (int kc = 0; kc < NCH; kc++) {
            int buf = kc & 1;
            bool more = (kc + 1 < NCH);
            if (more) {
                unsigned dst = sAu + ((buf ^ 1) * SA_BUF + arow * SA_STR + abase) * 4;
                const unsigned* src = hsrc + (kc + 1) * CHKP;
#pragma unroll
                for (int j = 0; j < 3; j++) cpasync16(dst + j * 16, src + j * 4);
                cpasync_commit();
            }
            const unsigned* Ab = sA + buf * SA_BUF;
            int row = wm * 16 + (lane >> 2);
            const unsigned* Ap = Ab + row * SA_STR;
#pragma unroll
            for (int ts = 0; ts < 12; ts++) {
                int kpl = ts * 8 + (lane & 3);
                unsigned a[4];
                a[0] = Ap[kpl];                  a[1] = Ap[8 * SA_STR + kpl];
                a[2] = Ap[kpl + 4];              a[3] = Ap[8 * SA_STR + kpl + 4];
                int kpf = kc * CHKP + kpl;
#pragma unroll
                for (int ni = 0; ni < 2; ni++) {
                    int cb = wn * 16 + ni * 8 + (lane >> 2);
                    unsigned bh[2];
                    bh[0] = sB[kpf * 68 + cb];
                    bh[1] = sB[(kpf + 4) * 68 + cb];
                    mma16(acc[ni], a, bh);
                }
            }
            if (more) cpasync_wait<0>();
            __syncthreads();
        }

        // fused sLSTM epilogue; h_new written back as fp16x2 plane
#pragma unroll
        for (int ni = 0; ni < 2; ni++) {
            float d0 = acc[ni][0], d1 = acc[ni][1];
            float d2 = acc[ni][2], d3 = acc[ni][3];
            float p0 = __shfl_xor_sync(0xffffffffu, d0, 1);
            float p1 = __shfl_xor_sync(0xffffffffu, d1, 1);
            float p2 = __shfl_xor_sync(0xffffffffu, d2, 1);
            float p3 = __shfl_xor_sync(0xffffffffu, d3, 1);
            if ((lane & 1) == 0) {
                int c = cb0 + wn * 16 + ni * 8 + (lane & 3) * 2;
                bool valid = (c < NCOL);
                int e = c >> 2;
                int br = b0 + wm * 16 + (lane >> 2);
                float hvv[2];
#pragma unroll
                for (int rr = 0; rr < 2; rr++) {
                    int bb = br + rr * 8;
                    float4 pr = make_float4(0.f, 0.f, 0.f, 0.f);
                    if (valid) pr = *(const float4*)(g_pre + (size_t)(s * BB + bb) * NCOL + c);
                    float it = (rr ? d2 : d0) + pr.x;
                    float ft = (rr ? d3 : d1) + pr.y;
                    float zt = (rr ? p2 : p0) + pr.z;
                    float ot = (rr ? p3 : p1) + pr.w;
                    float mo = smst[ni][rr];
                    float mn = fmaxf(ft + mo, it);
                    float iv = expf(it - mn);
                    float fv = expf(ft + mo - mn);
                    float cn = fv * scst[ni][rr] + iv * tanhf(zt);
                    float nn = fv * snst[ni][rr] + iv;
                    float sg = 1.f / (1.f + expf(-ot));
                    float hv = sg * cn / fmaxf(nn, 1e-6f);
                    scst[ni][rr] = cn; snst[ni][rr] = nn; smst[ni][rr] = mn;
                    hvv[rr] = valid ? hv : 0.f;
                    if (valid) g_x[(size_t)(bb * SS + s) * DD + e] += hv;
                }
                // pack (e, e+1): lane (lane&3)==0 holds e (even), partner lane^2 holds e+1
                float o0 = __shfl_xor_sync(0x55555555u, hvv[0], 2);
                float o1 = __shfl_xor_sync(0x55555555u, hvv[1], 2);
                if ((lane & 3) == 0) {
                    int kp = e >> 1;
                    hnxt[(size_t)br * KP + kp]       = pack_hi2(hvv[0], o0);
                    hnxt[(size_t)(br + 8) * KP + kp] = pack_hi2(hvv[1], o1);
                }
            }
        }
        ++target; group_barrier(grp, target);
    }
}

// ---------------- batchnorm statistics ----------------
__global__ void k_bnstats() {
    int d = blockIdx.x;
    __shared__ float r1[256], r2[256];
    float s1 = 0.f, s2 = 0.f;
    for (int r = threadIdx.x; r < ROWS; r += 256) {
        float v = g_x[(size_t)r * DD + d];
        s1 += v; s2 += v * v;
    }
    r1[threadIdx.x] = s1; r2[threadIdx.x] = s2; __syncthreads();
    for (int o = 128; o > 0; o >>= 1) {
        if (threadIdx.x < o) { r1[threadIdx.x] += r1[threadIdx.x + o]; r2[threadIdx.x] += r2[threadIdx.x + o]; }
        __syncthreads();
    }
    if (threadIdx.x == 0) {
        float mu = r1[0] / (float)ROWS;
        float var = r2[0] / (float)ROWS - mu * mu;
        g_mean[d] = mu;
        g_rstd[d] = rsqrtf(var + 1e-5f);
    }
}

// ---------------- final projection ----------------
__global__ void k_final(const float* __restrict__ w6, const float* __restrict__ b6,
                        const float* __restrict__ bng, const float* __restrict__ bnb,
                        float* __restrict__ out) {
    int bp = blockIdx.x;
    int b = bp / PP, p = bp % PP;
    __shared__ float r0[128], r1[128];
    float a0 = 0.f, a1 = 0.f;
    for (int i = threadIdx.x; i < OUTIN; i += 128) {
        int flat = p * OUTIN + i;
        int d = flat / SS, s = flat % SS;
        float v = g_x[(size_t)(b * SS + s) * DD + d];
        float xn = (v - g_mean[d]) * g_rstd[d] * bng[d] + bnb[d];
        a0 += xn * w6[i * 2 + 0];
        a1 += xn * w6[i * 2 + 1];
    }
    r0[threadIdx.x] = a0; r1[threadIdx.x] = a1; __syncthreads();
    for (int o = 64; o > 0; o >>= 1) {
        if (threadIdx.x < o) { r0[threadIdx.x] += r0[threadIdx.x + o]; r1[threadIdx.x] += r1[threadIdx.x + o]; }
        __syncthreads();
    }
    if (threadIdx.x == 0) {
        out[bp * 2 + 0] = tanhf(r0[0] + b6[0]);
        out[bp * 2 + 1] = tanhf(r1[0] + b6[1]);
    }
}

// ---------------- launch ----------------
extern "C" void kernel_launch(void* const* d_in, const int* in_sizes, int n_in,
                              void* d_out, int out_size) {
    const float* inp = (const float*)d_in[0];
    const float* Wg  = (const float*)d_in[1];
    const float* Rg  = (const float*)d_in[2];
    const float* bgp = (const float*)d_in[3];
    const float* lng = (const float*)d_in[4];
    const float* lnb = (const float*)d_in[5];
    const float* bng = (const float*)d_in[6];
    const float* bnb = (const float*)d_in[7];
    const float* w6  = (const float*)d_in[8];
    const float* b6  = (const float*)d_in[9];
    float* out = (float*)d_out;

    cudaFuncSetAttribute(k_scan, cudaFuncAttributeMaxDynamicSharedMemorySize, SCAN_SMEM);

    const int NWQ = 4 * KP * DD;
    k_reshape<<<(ROWS * DD + 255) / 256, 256>>>(inp);
    for (int l = 0; l < NBL; l++) {
        k_convW<<<(NWQ + 255) / 256, 256>>>(Wg + (size_t)l * 4 * DD * DD);
        k_convR<<<(KP * NCOL + 255) / 256, 256>>>(Rg + (size_t)l * 4 * DD * DD);
        k_layernorm<<<ROWS, 128>>>(lng + l * DD, lnb + l * DD);
        k_wgemm<<<dim3(9, 160, 4), 128>>>(bgp + (size_t)l * 4 * DD);
        k_scan<<<dim3(CBLK, BBLK), 512, SCAN_SMEM>>>();
    }
    k_bnstats<<<DD, 256>>>();
    k_final<<<BB * PP, 128>>>(w6, b6, bng, bnb, out);
}